// round 5
// baseline (speedup 1.0000x reference)
#include <cuda_runtime.h>
#include <cuda_bf16.h>
#include <cstddef>

#define FIELD 39
#define EMB   32
#define DIN   (FIELD * EMB)   // 1248
#define H     400
#define BMAX  16384

// Scratch (allocation-free rule: __device__ globals)
__device__ __align__(128) float g_emb[(size_t)BMAX * DIN];  // ~82 MB
__device__ __align__(128) float g_h1 [(size_t)BMAX * H];    // ~26 MB

// ---------------------------------------------------------------------------
// Kernel 1: embedding gather (writes deep input), first-order, second-order.
// One warp per batch row; lane = embedding dim. Gathers are 128B coalesced.
// ---------------------------------------------------------------------------
__global__ __launch_bounds__(256) void gather_fm_kernel(
    const int*   __restrict__ fidx,
    const float* __restrict__ fval,
    const float* __restrict__ etab,
    const float* __restrict__ btab,
    float* __restrict__ out_first,   // [B, 39]
    float* __restrict__ out_second,  // [B, 32]
    int B)
{
    int gwarp = (blockIdx.x * blockDim.x + threadIdx.x) >> 5;
    int lane  = threadIdx.x & 31;
    if (gwarp >= B) return;
    const int b = gwarp;

    const int*   ip = fidx + (size_t)b * FIELD;
    const float* vp = fval + (size_t)b * FIELD;
    float* erow = g_emb + (size_t)b * DIN;

    float s = 0.f, ss = 0.f;
    #pragma unroll 4
    for (int f = 0; f < FIELD; f++) {
        int   idx = __ldg(ip + f);                       // uniform broadcast
        float val = __ldg(vp + f);
        float v   = __ldg(etab + (size_t)idx * EMB + lane) * val;
        erow[f * EMB + lane] = v;
        s  += v;
        ss += v * v;
    }
    out_second[(size_t)b * EMB + lane] = 0.5f * (s * s - ss);

    // first_order[b,f] = bias[idx[b,f]] * value[b,f]
    for (int f = lane; f < FIELD; f += 32) {
        int idx = __ldg(ip + f);
        out_first[(size_t)b * FIELD + f] = __ldg(btab + idx) * __ldg(vp + f);
    }
}

// ---------------------------------------------------------------------------
// Kernel 2/3: C[M,N] = act(A[M,K] * W[N,K]^T + bias[N])
// Tile 128x128x16, 256 threads, 8x8 per-thread microtile.
// M assumed multiple of 128, K multiple of 16. N handled with masking.
// ---------------------------------------------------------------------------
#define BM 128
#define BN 128
#define BK 16
#define SPAD 132   // padded smem row (floats), keeps 16B alignment for LDS.128

template<bool RELU>
__global__ __launch_bounds__(256) void sgemm_nt(
    const float* __restrict__ A,
    const float* __restrict__ W,
    const float* __restrict__ bias,
    float* __restrict__ C,
    int M, int N, int K)
{
    __shared__ float As[BK][SPAD];
    __shared__ float Ws[BK][SPAD];

    const int tid = threadIdx.x;
    const int tx  = tid & 15;       // 0..15 -> N
    const int ty  = tid >> 4;       // 0..15 -> M
    const int bm  = blockIdx.y * BM;
    const int bn  = blockIdx.x * BN;

    // global->smem load mapping: 512 float4 per tile, 2 per thread
    const int lrow = tid >> 2;           // 0..63
    const int lk4  = (tid & 3) * 4;      // 0,4,8,12

    float acc[8][8];
    #pragma unroll
    for (int i = 0; i < 8; i++)
        #pragma unroll
        for (int j = 0; j < 8; j++) acc[i][j] = 0.f;

    for (int k0 = 0; k0 < K; k0 += BK) {
        // A tile (always in-bounds: M multiple of 128, K multiple of 16)
        #pragma unroll
        for (int r = 0; r < 2; r++) {
            int row = lrow + r * 64;
            float4 v = *(const float4*)(A + (size_t)(bm + row) * K + k0 + lk4);
            As[lk4 + 0][row] = v.x;
            As[lk4 + 1][row] = v.y;
            As[lk4 + 2][row] = v.z;
            As[lk4 + 3][row] = v.w;
        }
        // W tile (zero-fill rows beyond N)
        #pragma unroll
        for (int r = 0; r < 2; r++) {
            int row = lrow + r * 64;
            int n   = bn + row;
            float4 v = make_float4(0.f, 0.f, 0.f, 0.f);
            if (n < N)
                v = *(const float4*)(W + (size_t)n * K + k0 + lk4);
            Ws[lk4 + 0][row] = v.x;
            Ws[lk4 + 1][row] = v.y;
            Ws[lk4 + 2][row] = v.z;
            Ws[lk4 + 3][row] = v.w;
        }
        __syncthreads();

        #pragma unroll
        for (int k = 0; k < BK; k++) {
            float a[8], b[8];
            *(float4*)&a[0] = *(const float4*)&As[k][ty * 8];
            *(float4*)&a[4] = *(const float4*)&As[k][ty * 8 + 4];
            *(float4*)&b[0] = *(const float4*)&Ws[k][tx * 8];
            *(float4*)&b[4] = *(const float4*)&Ws[k][tx * 8 + 4];
            #pragma unroll
            for (int i = 0; i < 8; i++)
                #pragma unroll
                for (int j = 0; j < 8; j++)
                    acc[i][j] = fmaf(a[i], b[j], acc[i][j]);
        }
        __syncthreads();
    }

    // Epilogue: +bias, optional ReLU, masked store (ldc = N)
    #pragma unroll
    for (int i = 0; i < 8; i++) {
        int m = bm + ty * 8 + i;
        #pragma unroll
        for (int j = 0; j < 8; j++) {
            int n = bn + tx * 8 + j;
            if (n < N) {
                float v = acc[i][j] + __ldg(bias + n);
                if (RELU) v = fmaxf(v, 0.f);
                C[(size_t)m * N + n] = v;
            }
        }
    }
}

// ---------------------------------------------------------------------------
// Kernel 4: final linear over concat([first(39), second(32), deep(400)])
// One warp per batch row; warp-reduce the 471-wide dot product.
// ---------------------------------------------------------------------------
__global__ __launch_bounds__(256) void final_kernel(
    const float* __restrict__ first,   // [B,39]
    const float* __restrict__ second,  // [B,32]
    const float* __restrict__ deep,    // [B,400]
    const float* __restrict__ fW,      // [1,471]
    const float* __restrict__ fb,      // [1]
    float* __restrict__ out,           // [B,1]
    int B)
{
    int gwarp = (blockIdx.x * blockDim.x + threadIdx.x) >> 5;
    int lane  = threadIdx.x & 31;
    if (gwarp >= B) return;
    const int b = gwarp;

    float acc = 0.f;
    for (int i = lane; i < FIELD; i += 32)
        acc = fmaf(first[(size_t)b * FIELD + i], __ldg(fW + i), acc);
    acc = fmaf(second[(size_t)b * EMB + lane], __ldg(fW + FIELD + lane), acc);
    for (int i = lane; i < H; i += 32)
        acc = fmaf(deep[(size_t)b * H + i], __ldg(fW + FIELD + EMB + i), acc);

    #pragma unroll
    for (int o = 16; o > 0; o >>= 1)
        acc += __shfl_xor_sync(0xFFFFFFFFu, acc, o);

    if (lane == 0) out[b] = acc + __ldg(fb);
}

// ---------------------------------------------------------------------------
extern "C" void kernel_launch(void* const* d_in, const int* in_sizes, int n_in,
                              void* d_out, int out_size)
{
    const int*   fidx = (const int*)  d_in[0];
    const float* fval = (const float*)d_in[1];
    const float* etab = (const float*)d_in[2];
    const float* btab = (const float*)d_in[3];
    const float* W1   = (const float*)d_in[4];
    const float* b1   = (const float*)d_in[5];
    const float* W2   = (const float*)d_in[6];
    const float* b2   = (const float*)d_in[7];
    const float* fW   = (const float*)d_in[8];
    const float* fb   = (const float*)d_in[9];
    float* out = (float*)d_out;

    const int B = in_sizes[0] / FIELD;   // 16384

    // Output layout: tuple members flattened + concatenated
    float* out0 = out;                   // output       [B,1]
    float* out1 = out + (size_t)B;       // first_order  [B,39]
    float* out2 = out + (size_t)B * 40;  // second_order [B,32]
    float* out3 = out + (size_t)B * 72;  // deep_y       [B,400]

    float* p_emb = nullptr;
    float* p_h1  = nullptr;
    cudaGetSymbolAddress((void**)&p_emb, g_emb);
    cudaGetSymbolAddress((void**)&p_h1,  g_h1);

    // 1) gather + FM first/second order
    gather_fm_kernel<<<(B + 7) / 8, 256>>>(fidx, fval, etab, btab, out1, out2, B);

    // 2) deep layer 1: relu(emb @ W1^T + b1) -> g_h1
    dim3 grid1((H + BN - 1) / BN, B / BM);
    sgemm_nt<true><<<grid1, 256>>>(p_emb, W1, b1, p_h1, B, H, DIN);

    // 3) deep layer 2: relu(h1 @ W2^T + b2) -> out3 (deep_y)
    sgemm_nt<true><<<grid1, 256>>>(p_h1, W2, b2, out3, B, H, H);

    // 4) final linear over concat
    final_kernel<<<(B + 7) / 8, 256>>>(out1, out2, out3, fW, fb, out0, B);
}

// round 6
// speedup vs baseline: 2.1345x; 2.1345x over previous
#include <cuda_runtime.h>
#include <cuda_bf16.h>
#include <cstddef>
#include <cstdint>

#define FIELD 39
#define EMB   32
#define DIN   (FIELD * EMB)   // 1248
#define H     400
#define BMAX  16384

// Scratch (allocation-free rule: __device__ globals)
__device__ __align__(128) float g_emb[(size_t)BMAX * DIN];  // ~82 MB
__device__ __align__(128) float g_h1 [(size_t)BMAX * H];    // ~26 MB

// ---------------------------------------------------------------------------
// Kernel 1: embedding gather + FM first/second order. One warp per row.
// ---------------------------------------------------------------------------
__global__ __launch_bounds__(256) void gather_fm_kernel(
    const int*   __restrict__ fidx,
    const float* __restrict__ fval,
    const float* __restrict__ etab,
    const float* __restrict__ btab,
    float* __restrict__ out_first,   // [B, 39]
    float* __restrict__ out_second,  // [B, 32]
    int B)
{
    int gwarp = (blockIdx.x * blockDim.x + threadIdx.x) >> 5;
    int lane  = threadIdx.x & 31;
    if (gwarp >= B) return;
    const int b = gwarp;

    const int*   ip = fidx + (size_t)b * FIELD;
    const float* vp = fval + (size_t)b * FIELD;
    float* erow = g_emb + (size_t)b * DIN;

    float s = 0.f, ss = 0.f;
    #pragma unroll 4
    for (int f = 0; f < FIELD; f++) {
        int   idx = __ldg(ip + f);
        float val = __ldg(vp + f);
        float v   = __ldg(etab + (size_t)idx * EMB + lane) * val;
        erow[f * EMB + lane] = v;
        s  += v;
        ss += v * v;
    }
    out_second[(size_t)b * EMB + lane] = 0.5f * (s * s - ss);

    for (int f = lane; f < FIELD; f += 32) {
        int idx = __ldg(ip + f);
        out_first[(size_t)b * FIELD + f] = __ldg(btab + idx) * __ldg(vp + f);
    }
}

// ---------------------------------------------------------------------------
// TF32 tensor-core GEMM:  C[M,N] = act(A[M,K] @ W[N,K]^T + bias[N])
// CTA tile 256x128x8, 8 warps (4x2) of 64x64, double-buffered smem,
// ldmatrix.x4 quadrant loads, mma.sync.m16n8k8.tf32.
// M % 256 == 0, K % 8 == 0 assumed; N masked.
// ---------------------------------------------------------------------------
#define GBM 256
#define GBN 128
#define GPAD 12   // floats per smem row (8 used, stride 48B -> conflict-free ldmatrix)

__device__ __forceinline__ uint32_t f2tf(float f) {
    uint32_t r;
    asm("cvt.rna.tf32.f32 %0, %1;" : "=r"(r) : "f"(f));
    return r;
}

__device__ __forceinline__ void ldsm_x4(uint32_t& r0, uint32_t& r1,
                                        uint32_t& r2, uint32_t& r3, uint32_t addr) {
    asm volatile("ldmatrix.sync.aligned.m8n8.x4.shared.b16 {%0,%1,%2,%3}, [%4];"
                 : "=r"(r0), "=r"(r1), "=r"(r2), "=r"(r3) : "r"(addr));
}

__device__ __forceinline__ void mma_tf32(float* c, const uint32_t* a,
                                         uint32_t b0, uint32_t b1) {
    asm volatile(
        "mma.sync.aligned.m16n8k8.row.col.f32.tf32.tf32.f32 "
        "{%0,%1,%2,%3}, {%4,%5,%6,%7}, {%8,%9}, {%0,%1,%2,%3};"
        : "+f"(c[0]), "+f"(c[1]), "+f"(c[2]), "+f"(c[3])
        : "r"(a[0]), "r"(a[1]), "r"(a[2]), "r"(a[3]), "r"(b0), "r"(b1));
}

__device__ __forceinline__ uint4 pack_tf32(float4 v) {
    uint4 u;
    u.x = f2tf(v.x); u.y = f2tf(v.y); u.z = f2tf(v.z); u.w = f2tf(v.w);
    return u;
}

template<bool RELU>
__global__ __launch_bounds__(256, 1) void tf32_gemm_nt(
    const float* __restrict__ A,
    const float* __restrict__ W,
    const float* __restrict__ bias,
    float* __restrict__ C,
    int M, int N, int K)
{
    __shared__ uint32_t As[2][GBM * GPAD];   // [m][k] tf32, 48B rows
    __shared__ uint32_t Ws[2][GBN * GPAD];   // [n][k] tf32

    const int tid  = threadIdx.x;
    const int lane = tid & 31;
    const int wid  = tid >> 5;
    const int warp_m = wid >> 1;   // 0..3
    const int warp_n = wid & 1;    // 0..1
    const int bm = blockIdx.y * GBM;
    const int bn = blockIdx.x * GBN;

    const uint32_t sA = (uint32_t)__cvta_generic_to_shared(&As[0][0]);
    const uint32_t sW = (uint32_t)__cvta_generic_to_shared(&Ws[0][0]);
    const uint32_t ABUF = GBM * GPAD * 4;   // bytes per A buffer
    const uint32_t WBUF = GBN * GPAD * 4;

    // ldmatrix x4 lane addressing (quadrant layout -> tf32 fragments)
    const int q = lane >> 3, r = lane & 7;
    // A quadrants: q0=(rows 0-7, k0-3) q1=(rows 8-15, k0-3) q2=(rows 0-7, k4-7) q3=(8-15, k4-7)
    const uint32_t aAddrBase =
        sA + (uint32_t)((warp_m * 64 + (q & 1) * 8 + r) * GPAD) * 4 + (q >> 1) * 16;
    // B quadrants: q0=(n 0-7, k0-3) q1=(n 0-7, k4-7) q2=(n 8-15, k0-3) q3=(n 8-15, k4-7)
    const uint32_t bAddrBase =
        sW + (uint32_t)((warp_n * 64 + (q >> 1) * 8 + r) * GPAD) * 4 + (q & 1) * 16;

    // global load mapping
    const int arow  = tid;                 // A: one 8-float row per thread
    const int brow  = tid >> 1;            // W: 2 threads per 8-float row
    const int bhalf = tid & 1;
    const float* Aptr = A + (size_t)(bm + arow) * K;
    const float* Wptr = W + (size_t)(bn + brow) * K + bhalf * 4;
    const bool bvalid = (bn + brow) < N;

    float acc[4][8][4];
    #pragma unroll
    for (int i = 0; i < 4; i++)
        #pragma unroll
        for (int j = 0; j < 8; j++)
            #pragma unroll
            for (int c = 0; c < 4; c++) acc[i][j][c] = 0.f;

    // prologue: k-step 0 into regs, then smem buf 0
    float4 ra0 = *(const float4*)(Aptr);
    float4 ra1 = *(const float4*)(Aptr + 4);
    float4 rb  = bvalid ? *(const float4*)(Wptr) : make_float4(0.f, 0.f, 0.f, 0.f);

    *(uint4*)&As[0][arow * GPAD]              = pack_tf32(ra0);
    *(uint4*)&As[0][arow * GPAD + 4]          = pack_tf32(ra1);
    *(uint4*)&Ws[0][brow * GPAD + bhalf * 4]  = pack_tf32(rb);
    __syncthreads();

    const int nk = K >> 3;
    for (int kk = 0; kk < nk; kk++) {
        const int cur = kk & 1;

        // prefetch next k-step (LDG early, covered by compute)
        if (kk + 1 < nk) {
            const int k0 = (kk + 1) << 3;
            ra0 = *(const float4*)(Aptr + k0);
            ra1 = *(const float4*)(Aptr + k0 + 4);
            rb  = bvalid ? *(const float4*)(Wptr + k0) : make_float4(0.f, 0.f, 0.f, 0.f);
        }

        // fragments
        uint32_t a[4][4], b[4][4];
        #pragma unroll
        for (int i = 0; i < 4; i++)
            ldsm_x4(a[i][0], a[i][1], a[i][2], a[i][3],
                    aAddrBase + cur * ABUF + (uint32_t)(i * 16 * GPAD * 4));
        #pragma unroll
        for (int j = 0; j < 4; j++)
            ldsm_x4(b[j][0], b[j][1], b[j][2], b[j][3],
                    bAddrBase + cur * WBUF + (uint32_t)(j * 16 * GPAD * 4));

        #pragma unroll
        for (int i = 0; i < 4; i++)
            #pragma unroll
            for (int jt = 0; jt < 8; jt++)
                mma_tf32(acc[i][jt], a[i],
                         b[jt >> 1][(jt & 1) * 2], b[jt >> 1][(jt & 1) * 2 + 1]);

        // stage next k-step into alternate buffer
        if (kk + 1 < nk) {
            const int nxt = cur ^ 1;
            *(uint4*)&As[nxt][arow * GPAD]             = pack_tf32(ra0);
            *(uint4*)&As[nxt][arow * GPAD + 4]         = pack_tf32(ra1);
            *(uint4*)&Ws[nxt][brow * GPAD + bhalf * 4] = pack_tf32(rb);
        }
        __syncthreads();
    }

    // epilogue: c0,c1 -> (row g, cols 2t,2t+1); c2,c3 -> row g+8
    const int g  = lane >> 2;
    const int t4 = lane & 3;
    #pragma unroll
    for (int i = 0; i < 4; i++) {
        const int row0 = bm + warp_m * 64 + i * 16 + g;
        #pragma unroll
        for (int jt = 0; jt < 8; jt++) {
            const int col = bn + warp_n * 64 + jt * 8 + t4 * 2;
            if (col < N) {  // N % 8 == 0: whole n8 tile in/out together
                const float bs0 = __ldg(bias + col);
                const float bs1 = __ldg(bias + col + 1);
                float v0 = acc[i][jt][0] + bs0;
                float v1 = acc[i][jt][1] + bs1;
                float v2 = acc[i][jt][2] + bs0;
                float v3 = acc[i][jt][3] + bs1;
                if (RELU) {
                    v0 = fmaxf(v0, 0.f); v1 = fmaxf(v1, 0.f);
                    v2 = fmaxf(v2, 0.f); v3 = fmaxf(v3, 0.f);
                }
                *(float2*)(C + (size_t)row0 * N + col)       = make_float2(v0, v1);
                *(float2*)(C + (size_t)(row0 + 8) * N + col) = make_float2(v2, v3);
            }
        }
    }
}

// ---------------------------------------------------------------------------
// Final linear over concat([first(39), second(32), deep(400)])
// ---------------------------------------------------------------------------
__global__ __launch_bounds__(256) void final_kernel(
    const float* __restrict__ first,
    const float* __restrict__ second,
    const float* __restrict__ deep,
    const float* __restrict__ fW,
    const float* __restrict__ fb,
    float* __restrict__ out,
    int B)
{
    int gwarp = (blockIdx.x * blockDim.x + threadIdx.x) >> 5;
    int lane  = threadIdx.x & 31;
    if (gwarp >= B) return;
    const int b = gwarp;

    float acc = 0.f;
    for (int i = lane; i < FIELD; i += 32)
        acc = fmaf(first[(size_t)b * FIELD + i], __ldg(fW + i), acc);
    acc = fmaf(second[(size_t)b * EMB + lane], __ldg(fW + FIELD + lane), acc);
    for (int i = lane; i < H; i += 32)
        acc = fmaf(deep[(size_t)b * H + i], __ldg(fW + FIELD + EMB + i), acc);

    #pragma unroll
    for (int o = 16; o > 0; o >>= 1)
        acc += __shfl_xor_sync(0xFFFFFFFFu, acc, o);

    if (lane == 0) out[b] = acc + __ldg(fb);
}

// ---------------------------------------------------------------------------
extern "C" void kernel_launch(void* const* d_in, const int* in_sizes, int n_in,
                              void* d_out, int out_size)
{
    const int*   fidx = (const int*)  d_in[0];
    const float* fval = (const float*)d_in[1];
    const float* etab = (const float*)d_in[2];
    const float* btab = (const float*)d_in[3];
    const float* W1   = (const float*)d_in[4];
    const float* b1   = (const float*)d_in[5];
    const float* W2   = (const float*)d_in[6];
    const float* b2   = (const float*)d_in[7];
    const float* fW   = (const float*)d_in[8];
    const float* fb   = (const float*)d_in[9];
    float* out = (float*)d_out;

    const int B = in_sizes[0] / FIELD;   // 16384

    float* out0 = out;                   // output       [B,1]
    float* out1 = out + (size_t)B;       // first_order  [B,39]
    float* out2 = out + (size_t)B * 40;  // second_order [B,32]
    float* out3 = out + (size_t)B * 72;  // deep_y       [B,400]

    float* p_emb = nullptr;
    float* p_h1  = nullptr;
    cudaGetSymbolAddress((void**)&p_emb, g_emb);
    cudaGetSymbolAddress((void**)&p_h1,  g_h1);

    // 1) gather + FM terms
    gather_fm_kernel<<<(B + 7) / 8, 256>>>(fidx, fval, etab, btab, out1, out2, B);

    // 2) deep layer 1: relu(emb @ W1^T + b1)
    dim3 grid1((H + GBN - 1) / GBN, B / GBM);
    tf32_gemm_nt<true><<<grid1, 256>>>(p_emb, W1, b1, p_h1, B, H, DIN);

    // 3) deep layer 2: relu(h1 @ W2^T + b2) -> deep_y
    tf32_gemm_nt<true><<<grid1, 256>>>(p_h1, W2, b2, out3, B, H, H);

    // 4) final linear
    final_kernel<<<(B + 7) / 8, 256>>>(out1, out2, out3, fW, fb, out0, B);
}